// round 7
// baseline (speedup 1.0000x reference)
#include <cuda_runtime.h>
#include <stdint.h>
#include <math.h>
#include <float.h>

#define NMAX   32768
#define KNN    12
#define WID    192
#define CONDD  64
#define IN0    115      // 51 PE + 64 cond
#define MIXD   390      // 192 + 192 + 6
#define NL     4
#define BRP    16       // rows per block, prep
#define BRL    16       // rows per block, layer

#define GRID   64
#define CELLS  (GRID * GRID * GRID)
#define GMINF  (-4.0f)
#define GH     0.125f
#define GINVH  8.0f

// ---------------- scratch (device globals; no allocations allowed) ----------
__device__ int    g_knn[NMAX * KNN];
__device__ float  g_rel[NMAX * 6];
__device__ float  g_h[2][NMAX * WID];
__device__ float  g_gamma[NL * WID];
__device__ float  g_beta[NL * WID];

__device__ int    g_cnt[CELLS];
__device__ int    g_start[CELLS + 1];
__device__ int    g_cell[NMAX];
__device__ int    g_rank[NMAX];
__device__ float4 g_pts4[NMAX];       // sorted coords + |p|^2
__device__ int    g_sorted_orig[NMAX];

// ---------------- grid build -------------------------------------------------
__device__ __forceinline__ int cell_coord(float v) {
    int c = (int)floorf((v - GMINF) * GINVH);
    return min(GRID - 1, max(0, c));
}

__global__ void grid_zero_kernel() {
    int i = blockIdx.x * blockDim.x + threadIdx.x;
    if (i < CELLS) g_cnt[i] = 0;
}

__global__ void grid_hist_kernel(const float* __restrict__ x, int n) {
    int i = blockIdx.x * blockDim.x + threadIdx.x;
    if (i >= n) return;
    int cx = cell_coord(x[i * 3 + 0]);
    int cy = cell_coord(x[i * 3 + 1]);
    int cz = cell_coord(x[i * 3 + 2]);
    int c = (cz * GRID + cy) * GRID + cx;
    g_cell[i] = c;
    g_rank[i] = atomicAdd(&g_cnt[c], 1);
}

__global__ void grid_scan_kernel() {  // single block, 1024 threads, 256 cells each
    __shared__ int sh[1024];
    int tid = threadIdx.x;
    int base = tid * (CELLS / 1024);
    int s = 0;
    for (int k = 0; k < CELLS / 1024; k++) s += g_cnt[base + k];
    sh[tid] = s;
    __syncthreads();
    for (int off = 1; off < 1024; off <<= 1) {
        int v = (tid >= off) ? sh[tid - off] : 0;
        __syncthreads();
        sh[tid] += v;
        __syncthreads();
    }
    int run = sh[tid] - s;  // exclusive base
    for (int k = 0; k < CELLS / 1024; k++) {
        g_start[base + k] = run;
        run += g_cnt[base + k];
    }
    if (tid == 1023) g_start[CELLS] = sh[1023];
}

__global__ void grid_scatter_kernel(const float* __restrict__ x, int n) {
    int i = blockIdx.x * blockDim.x + threadIdx.x;
    if (i >= n) return;
    float px = x[i * 3 + 0], py = x[i * 3 + 1], pz = x[i * 3 + 2];
    int pos = g_start[g_cell[i]] + g_rank[i];
    g_pts4[pos] = make_float4(px, py, pz, fmaf(px, px, fmaf(py, py, pz * pz)));
    g_sorted_orig[pos] = i;
}

// ---------------- kNN search: expanding shells with exact stop bound --------
__global__ void knn_search_kernel(int n) {
    const int t = blockIdx.x * blockDim.x + threadIdx.x;
    if (t >= n) return;
    const float4 q = g_pts4[t];
    const float qsq = q.w;
    const int cx = cell_coord(q.x);
    const int cy = cell_coord(q.y);
    const int cz = cell_coord(q.z);

    float bd[KNN];
    int   bi[KNN];
#pragma unroll
    for (int s = 0; s < KNN; s++) { bd[s] = 1e30f; bi[s] = 0; }
    float worst = 1e30f;
    int   wslot = 0;

    for (int r = 0; r < GRID; r++) {
        const int zlo = max(cz - r, 0), zhi = min(cz + r, GRID - 1);
        const int ylo = max(cy - r, 0), yhi = min(cy + r, GRID - 1);
        const int xlo = max(cx - r, 0), xhi = min(cx + r, GRID - 1);
        for (int iz = zlo; iz <= zhi; iz++) {
            const bool zedge = (iz == cz - r) || (iz == cz + r);
            for (int iy = ylo; iy <= yhi; iy++) {
                const bool yedge = (iy == cy - r) || (iy == cy + r);
                const int rowc = (iz * GRID + iy) * GRID;
                int j0, j1;
                if (zedge || yedge) {
                    j0 = g_start[rowc + xlo];
                    j1 = g_start[rowc + xhi + 1];
                } else {
                    j0 = 0; j1 = 0;
                    if (cx - r >= 0) {
                        int c = rowc + (cx - r);
                        j0 = g_start[c]; j1 = g_start[c + 1];
                    }
                    if (cx + r <= GRID - 1) {
                        int c = rowc + (cx + r);
                        int a0 = g_start[c], a1 = g_start[c + 1];
                        for (int j = a0; j < a1; j++) {
                            float4 p = g_pts4[j];
                            float d = qsq + p.w
                                    - 2.f * fmaf(q.x, p.x, fmaf(q.y, p.y, q.z * p.z));
                            if (d < worst && j != t) {
#pragma unroll
                                for (int s = 0; s < KNN; s++)
                                    if (s == wslot) { bd[s] = d; bi[s] = j; }
                                worst = bd[0]; wslot = 0;
#pragma unroll
                                for (int s = 1; s < KNN; s++)
                                    if (bd[s] > worst) { worst = bd[s]; wslot = s; }
                            }
                        }
                    }
                }
                for (int j = j0; j < j1; j++) {
                    float4 p = g_pts4[j];
                    float d = qsq + p.w
                            - 2.f * fmaf(q.x, p.x, fmaf(q.y, p.y, q.z * p.z));
                    if (d < worst && j != t) {
#pragma unroll
                        for (int s = 0; s < KNN; s++)
                            if (s == wslot) { bd[s] = d; bi[s] = j; }
                        worst = bd[0]; wslot = 0;
#pragma unroll
                        for (int s = 1; s < KNN; s++)
                            if (bd[s] > worst) { worst = bd[s]; wslot = s; }
                    }
                }
            }
        }
        // exact stop bound: min distance from q to unscanned region
        float b = FLT_MAX;
        if (zlo > 0)        b = fminf(b, q.z - (GMINF + zlo * GH));
        if (zhi < GRID - 1) b = fminf(b, (GMINF + (zhi + 1) * GH) - q.z);
        if (ylo > 0)        b = fminf(b, q.y - (GMINF + ylo * GH));
        if (yhi < GRID - 1) b = fminf(b, (GMINF + (yhi + 1) * GH) - q.y);
        if (xlo > 0)        b = fminf(b, q.x - (GMINF + xlo * GH));
        if (xhi < GRID - 1) b = fminf(b, (GMINF + (xhi + 1) * GH) - q.x);
        if (worst <= b * b) break;
    }

    const int orig = g_sorted_orig[t];
    float sx = 0.f, sy = 0.f, sz = 0.f, qx = 0.f, qy = 0.f, qz = 0.f;
#pragma unroll
    for (int s = 0; s < KNN; s++) {
        int pos = bi[s];
        float4 p = g_pts4[pos];
        g_knn[orig * KNN + s] = g_sorted_orig[pos];
        float rx = p.x - q.x;
        float ry = p.y - q.y;
        float rz = p.z - q.z;
        sx += rx; sy += ry; sz += rz;
        qx = fmaf(rx, rx, qx); qy = fmaf(ry, ry, qy); qz = fmaf(rz, rz, qz);
    }
    const float inv = 1.f / (float)KNN;
    float mx = sx * inv, my = sy * inv, mz = sz * inv;
    g_rel[orig * 6 + 0] = mx;
    g_rel[orig * 6 + 1] = my;
    g_rel[orig * 6 + 2] = mz;
    g_rel[orig * 6 + 3] = sqrtf(fmaxf(qx * inv - mx * mx, 0.f));
    g_rel[orig * 6 + 4] = sqrtf(fmaxf(qy * inv - my * my, 0.f));
    g_rel[orig * 6 + 5] = sqrtf(fmaxf(qz * inv - mz * mz, 0.f));
}

// ---------------- FiLM gamma/beta (depends only on z); one block per layer --
__global__ void film_kernel(const float* __restrict__ z,
                            const float* __restrict__ Wg, const float* __restrict__ bg,
                            const float* __restrict__ Wb, const float* __restrict__ bb) {
    int c = threadIdx.x;  // 192
    int li = blockIdx.x;  // 4
    float ga = bg[li * WID + c];
    float be = bb[li * WID + c];
    for (int k = 0; k < CONDD; k++) {
        float zk = z[k];
        ga = fmaf(zk, Wg[(li * CONDD + k) * WID + c], ga);
        be = fmaf(zk, Wb[(li * CONDD + k) * WID + c], be);
    }
    g_gamma[li * WID + c] = ga;
    g_beta[li * WID + c]  = be;
}

__device__ __forceinline__ float silu(float a) {
    return a / (1.f + expf(-a));
}

// ---------------- prep: fourier PE + concat z + first dense + silu ----------
__global__ void prep_kernel(const float* __restrict__ x, const float* __restrict__ z,
                            const float* __restrict__ B0, const float* __restrict__ B1,
                            const float* __restrict__ B2,
                            const float* __restrict__ Wp, const float* __restrict__ bp,
                            int n) {
    __shared__ float fs[BRP * 120];
    const int row0 = blockIdx.x * BRP;
    const int tid = threadIdx.x;  // 192

    for (int e = tid; e < BRP * IN0; e += 192) {
        int r = e / IN0, i = e % IN0;
        int row = row0 + r;
        float v = 0.f;
        if (row < n) {
            if (i < 48) {
                int g = i >> 4, w = i & 15, col = w & 7;
                const float* B = (g == 0) ? B0 : ((g == 1) ? B1 : B2);
                float x0 = x[row * 3 + 0], x1 = x[row * 3 + 1], x2 = x[row * 3 + 2];
                float dot = fmaf(x0, B[col], fmaf(x1, B[8 + col], x2 * B[16 + col]));
                v = (w < 8) ? sinf(dot) : cosf(dot);
            } else if (i < 51) {
                v = x[row * 3 + (i - 48)];
            } else {
                v = z[i - 51];
            }
        }
        fs[r * 120 + i] = v;
    }
    for (int e = tid; e < BRP * 5; e += 192) {
        int r = e / 5, i = 115 + e % 5;
        fs[r * 120 + i] = 0.f;
    }
    __syncthreads();

    const int c = tid;
    float acc[BRP];
    float b = bp[c];
#pragma unroll
    for (int r = 0; r < BRP; r++) acc[r] = b;

    for (int ic = 0; ic < 28; ic++) {
        int i = ic * 4;
        float w0 = Wp[(i + 0) * WID + c];
        float w1 = Wp[(i + 1) * WID + c];
        float w2 = Wp[(i + 2) * WID + c];
        float w3 = Wp[(i + 3) * WID + c];
#pragma unroll
        for (int r = 0; r < BRP; r++) {
            float4 m = *(const float4*)&fs[r * 120 + i];
            acc[r] = fmaf(m.x, w0, acc[r]);
            acc[r] = fmaf(m.y, w1, acc[r]);
            acc[r] = fmaf(m.z, w2, acc[r]);
            acc[r] = fmaf(m.w, w3, acc[r]);
        }
    }
    for (int i = 112; i < 115; i++) {
        float w0 = Wp[i * WID + c];
#pragma unroll
        for (int r = 0; r < BRP; r++) acc[r] = fmaf(fs[r * 120 + i], w0, acc[r]);
    }

#pragma unroll
    for (int r = 0; r < BRP; r++) {
        int row = row0 + r;
        if (row < n) g_h[0][row * WID + c] = silu(acc[r]);
    }
}

// ---------------- one graph layer: gather+mean, mix GEMM, silu, FiLM --------
// 96 threads; each thread owns output columns c and c+96 (2 cols/thread).
__global__ void __launch_bounds__(96) layer_kernel(int src, int li,
                             const float* __restrict__ Wl_all,
                             const float* __restrict__ bl_all,
                             int n) {
    __shared__ float ms[BRL * 392];  // [h(192) | agg(192) | rel(6) | pad(2)]
    const float* __restrict__ hin = g_h[src];
    float* __restrict__ hout = g_h[1 - src];
    const float* __restrict__ Wl = Wl_all + (size_t)li * MIXD * WID;

    const int row0 = blockIdx.x * BRL;
    const int c = threadIdx.x;       // 0..95
    const int c1 = c + 96;
    const float inv = 1.f / (float)KNN;

    for (int r = 0; r < BRL; r++) {
        int row = row0 + r;
        float h0 = 0.f, h1 = 0.f, s0 = 0.f, s1 = 0.f;
        if (row < n) {
            h0 = hin[(size_t)row * WID + c];
            h1 = hin[(size_t)row * WID + c1];
            const int4* nbp = (const int4*)&g_knn[row * KNN];
            int4 na = nbp[0], nb = nbp[1], nc = nbp[2];
            int ids[KNN] = {na.x, na.y, na.z, na.w, nb.x, nb.y, nb.z, nb.w,
                            nc.x, nc.y, nc.z, nc.w};
#pragma unroll
            for (int j = 0; j < KNN; j++) {
                const float* hr = hin + (size_t)ids[j] * WID;
                s0 += hr[c];
                s1 += hr[c1];
            }
        }
        ms[r * 392 + c]        = h0;
        ms[r * 392 + c1]       = h1;
        ms[r * 392 + 192 + c]  = s0 * inv;
        ms[r * 392 + 192 + c1] = s1 * inv;
    }
    for (int e = c; e < BRL * 8; e += 96) {
        int r = e / 8, i = e % 8;
        int row = row0 + r;
        ms[r * 392 + 384 + i] = (i < 6 && row < n) ? g_rel[row * 6 + i] : 0.f;
    }
    __syncthreads();

    float acc0[BRL], acc1[BRL];
    {
        float b0 = bl_all[li * WID + c];
        float b1 = bl_all[li * WID + c1];
#pragma unroll
        for (int r = 0; r < BRL; r++) { acc0[r] = b0; acc1[r] = b1; }
    }

    for (int ic = 0; ic < 97; ic++) {  // 388 of 390
        int i = ic * 4;
        float w0 = Wl[(i + 0) * WID + c];
        float w1 = Wl[(i + 1) * WID + c];
        float w2 = Wl[(i + 2) * WID + c];
        float w3 = Wl[(i + 3) * WID + c];
        float v0 = Wl[(i + 0) * WID + c1];
        float v1 = Wl[(i + 1) * WID + c1];
        float v2 = Wl[(i + 2) * WID + c1];
        float v3 = Wl[(i + 3) * WID + c1];
#pragma unroll
        for (int r = 0; r < BRL; r++) {
            float4 m = *(const float4*)&ms[r * 392 + i];
            acc0[r] = fmaf(m.x, w0, acc0[r]);
            acc0[r] = fmaf(m.y, w1, acc0[r]);
            acc0[r] = fmaf(m.z, w2, acc0[r]);
            acc0[r] = fmaf(m.w, w3, acc0[r]);
            acc1[r] = fmaf(m.x, v0, acc1[r]);
            acc1[r] = fmaf(m.y, v1, acc1[r]);
            acc1[r] = fmaf(m.z, v2, acc1[r]);
            acc1[r] = fmaf(m.w, v3, acc1[r]);
        }
    }
    for (int i = 388; i < 390; i++) {
        float w0 = Wl[i * WID + c];
        float v0 = Wl[i * WID + c1];
#pragma unroll
        for (int r = 0; r < BRL; r++) {
            float m = ms[r * 392 + i];
            acc0[r] = fmaf(m, w0, acc0[r]);
            acc1[r] = fmaf(m, v0, acc1[r]);
        }
    }

    const float ga0 = g_gamma[li * WID + c];
    const float be0 = g_beta[li * WID + c];
    const float ga1 = g_gamma[li * WID + c1];
    const float be1 = g_beta[li * WID + c1];
#pragma unroll
    for (int r = 0; r < BRL; r++) {
        int row = row0 + r;
        if (row < n) {
            hout[(size_t)row * WID + c]  = fmaf(silu(acc0[r]), ga0, be0);
            hout[(size_t)row * WID + c1] = fmaf(silu(acc1[r]), ga1, be1);
        }
    }
}

// ---------------- output head: (h @ Wout + bout) * 0.01 ---------------------
__global__ void out_kernel(const float* __restrict__ Wout,
                           const float* __restrict__ bout,
                           float* __restrict__ out, int n) {
    const float* __restrict__ hin = g_h[0];  // after 4 layers: 0->1->0->1->0
    int gtid = blockIdx.x * blockDim.x + threadIdx.x;
    int warp = gtid >> 5;
    int lane = threadIdx.x & 31;
    if (warp >= n) return;
    float a0 = 0.f, a1 = 0.f, a2 = 0.f;
    for (int i = lane; i < WID; i += 32) {
        float h = hin[warp * WID + i];
        a0 = fmaf(h, Wout[i * 3 + 0], a0);
        a1 = fmaf(h, Wout[i * 3 + 1], a1);
        a2 = fmaf(h, Wout[i * 3 + 2], a2);
    }
#pragma unroll
    for (int o = 16; o; o >>= 1) {
        a0 += __shfl_down_sync(0xffffffffu, a0, o);
        a1 += __shfl_down_sync(0xffffffffu, a1, o);
        a2 += __shfl_down_sync(0xffffffffu, a2, o);
    }
    if (lane == 0) {
        out[warp * 3 + 0] = (a0 + bout[0]) * 0.01f;
        out[warp * 3 + 1] = (a1 + bout[1]) * 0.01f;
        out[warp * 3 + 2] = (a2 + bout[2]) * 0.01f;
    }
}

// ---------------- launch -----------------------------------------------------
extern "C" void kernel_launch(void* const* d_in, const int* in_sizes, int n_in,
                              void* d_out, int out_size) {
    const float* x    = (const float*)d_in[0];
    const float* z    = (const float*)d_in[1];
    const float* B0   = (const float*)d_in[2];
    const float* B1   = (const float*)d_in[3];
    const float* B2   = (const float*)d_in[4];
    const float* Wp   = (const float*)d_in[5];
    const float* bp   = (const float*)d_in[6];
    const float* Wl   = (const float*)d_in[7];
    const float* bl   = (const float*)d_in[8];
    const float* Wg   = (const float*)d_in[9];
    const float* bg   = (const float*)d_in[10];
    const float* Wb   = (const float*)d_in[11];
    const float* bb   = (const float*)d_in[12];
    const float* Wout = (const float*)d_in[13];
    const float* bout = (const float*)d_in[14];
    float* out = (float*)d_out;

    const int n = in_sizes[0] / 3;

    // spatial-grid kNN (64^3 cells)
    grid_zero_kernel<<<(CELLS + 255) / 256, 256>>>();
    grid_hist_kernel<<<(n + 255) / 256, 256>>>(x, n);
    grid_scan_kernel<<<1, 1024>>>();
    grid_scatter_kernel<<<(n + 255) / 256, 256>>>(x, n);
    knn_search_kernel<<<(n + 127) / 128, 128>>>(n);

    film_kernel<<<NL, WID>>>(z, Wg, bg, Wb, bb);
    prep_kernel<<<(n + BRP - 1) / BRP, WID>>>(x, z, B0, B1, B2, Wp, bp, n);

    int src = 0;
    for (int li = 0; li < NL; li++) {
        layer_kernel<<<(n + BRL - 1) / BRL, 96>>>(src, li, Wl, bl, n);
        src = 1 - src;
    }

    out_kernel<<<(n * 32 + 255) / 256, 256>>>(Wout, bout, out, n);
}

// round 8
// speedup vs baseline: 1.8140x; 1.8140x over previous
#include <cuda_runtime.h>
#include <stdint.h>
#include <math.h>
#include <float.h>

#define NMAX   32768
#define KNN    12
#define WID    192
#define CONDD  64
#define IN0    115      // 51 PE + 64 cond
#define MIXD   390      // 192 + 192 + 6
#define NL     4
#define BRP    16       // rows per block, prep
#define BRL    24       // rows per block, layer (12 f32x2 pairs)
#define NPAIR  12
#define SP     28       // msp stride in floats per k (112 B, 16B-aligned)

#define GRID   32
#define CELLS  (GRID * GRID * GRID)
#define GMINF  (-4.0f)
#define GH     0.25f
#define GINVH  4.0f

// ---------------- scratch (device globals; no allocations allowed) ----------
__device__ int    g_knn[NMAX * KNN];
__device__ float  g_rel[NMAX * 6];
__device__ float  g_h[2][NMAX * WID];
__device__ float  g_gamma[NL * WID];
__device__ float  g_beta[NL * WID];

__device__ int    g_cnt[CELLS];
__device__ int    g_start[CELLS + 1];
__device__ int    g_cell[NMAX];
__device__ int    g_rank[NMAX];
__device__ float4 g_pts4[NMAX];       // sorted coords + |p|^2
__device__ int    g_sorted_orig[NMAX];

// ---------------- f32x2 helpers ----------------------------------------------
__device__ __forceinline__ unsigned long long pk2(float v) {
    unsigned long long r;
    asm("mov.b64 %0, {%1, %1};" : "=l"(r) : "f"(v));
    return r;
}
__device__ __forceinline__ void fma2(unsigned long long& acc,
                                     unsigned long long m,
                                     unsigned long long w) {
    asm("fma.rn.f32x2 %0, %1, %2, %0;" : "+l"(acc) : "l"(m), "l"(w));
}
__device__ __forceinline__ void unpk2(unsigned long long v, float& lo, float& hi) {
    asm("mov.b64 {%0, %1}, %2;" : "=f"(lo), "=f"(hi) : "l"(v));
}

// ---------------- grid build -------------------------------------------------
__device__ __forceinline__ int cell_coord(float v) {
    int c = (int)floorf((v - GMINF) * GINVH);
    return min(GRID - 1, max(0, c));
}

__global__ void grid_zero_kernel() {
    int i = blockIdx.x * blockDim.x + threadIdx.x;
    if (i < CELLS) g_cnt[i] = 0;
}

__global__ void grid_hist_kernel(const float* __restrict__ x, int n) {
    int i = blockIdx.x * blockDim.x + threadIdx.x;
    if (i >= n) return;
    int cx = cell_coord(x[i * 3 + 0]);
    int cy = cell_coord(x[i * 3 + 1]);
    int cz = cell_coord(x[i * 3 + 2]);
    int c = (cz * GRID + cy) * GRID + cx;
    g_cell[i] = c;
    g_rank[i] = atomicAdd(&g_cnt[c], 1);
}

__global__ void grid_scan_kernel() {  // single block, 1024 threads, 32 cells each
    __shared__ int sh[1024];
    int tid = threadIdx.x;
    int base = tid * 32;
    int s = 0;
    for (int k = 0; k < 32; k++) s += g_cnt[base + k];
    sh[tid] = s;
    __syncthreads();
    for (int off = 1; off < 1024; off <<= 1) {
        int v = (tid >= off) ? sh[tid - off] : 0;
        __syncthreads();
        sh[tid] += v;
        __syncthreads();
    }
    int run = sh[tid] - s;  // exclusive base
    for (int k = 0; k < 32; k++) {
        g_start[base + k] = run;
        run += g_cnt[base + k];
    }
    if (tid == 1023) g_start[CELLS] = sh[1023];
}

__global__ void grid_scatter_kernel(const float* __restrict__ x, int n) {
    int i = blockIdx.x * blockDim.x + threadIdx.x;
    if (i >= n) return;
    float px = x[i * 3 + 0], py = x[i * 3 + 1], pz = x[i * 3 + 2];
    int pos = g_start[g_cell[i]] + g_rank[i];
    g_pts4[pos] = make_float4(px, py, pz, fmaf(px, px, fmaf(py, py, pz * pz)));
    g_sorted_orig[pos] = i;
}

// ---------------- kNN search: expanding shells with exact stop bound --------
__global__ void knn_search_kernel(int n) {
    const int t = blockIdx.x * blockDim.x + threadIdx.x;
    if (t >= n) return;
    const float4 q = g_pts4[t];
    const float qsq = q.w;
    const int cx = cell_coord(q.x);
    const int cy = cell_coord(q.y);
    const int cz = cell_coord(q.z);

    float bd[KNN];
    int   bi[KNN];
#pragma unroll
    for (int s = 0; s < KNN; s++) { bd[s] = 1e30f; bi[s] = 0; }
    float worst = 1e30f;
    int   wslot = 0;

    for (int r = 0; r < GRID; r++) {
        const int zlo = max(cz - r, 0), zhi = min(cz + r, GRID - 1);
        const int ylo = max(cy - r, 0), yhi = min(cy + r, GRID - 1);
        const int xlo = max(cx - r, 0), xhi = min(cx + r, GRID - 1);
        for (int iz = zlo; iz <= zhi; iz++) {
            const bool zedge = (iz == cz - r) || (iz == cz + r);
            for (int iy = ylo; iy <= yhi; iy++) {
                const bool yedge = (iy == cy - r) || (iy == cy + r);
                const int rowc = (iz * GRID + iy) * GRID;
                int j0, j1;
                if (zedge || yedge) {
                    j0 = g_start[rowc + xlo];
                    j1 = g_start[rowc + xhi + 1];
                } else {
                    j0 = 0; j1 = 0;
                    if (cx - r >= 0) {
                        int c = rowc + (cx - r);
                        j0 = g_start[c]; j1 = g_start[c + 1];
                    }
                    if (cx + r <= GRID - 1) {
                        int c = rowc + (cx + r);
                        int a0 = g_start[c], a1 = g_start[c + 1];
                        for (int j = a0; j < a1; j++) {
                            float4 p = g_pts4[j];
                            float d = qsq + p.w
                                    - 2.f * fmaf(q.x, p.x, fmaf(q.y, p.y, q.z * p.z));
                            if (d < worst && j != t) {
#pragma unroll
                                for (int s = 0; s < KNN; s++)
                                    if (s == wslot) { bd[s] = d; bi[s] = j; }
                                worst = bd[0]; wslot = 0;
#pragma unroll
                                for (int s = 1; s < KNN; s++)
                                    if (bd[s] > worst) { worst = bd[s]; wslot = s; }
                            }
                        }
                    }
                }
                for (int j = j0; j < j1; j++) {
                    float4 p = g_pts4[j];
                    float d = qsq + p.w
                            - 2.f * fmaf(q.x, p.x, fmaf(q.y, p.y, q.z * p.z));
                    if (d < worst && j != t) {
#pragma unroll
                        for (int s = 0; s < KNN; s++)
                            if (s == wslot) { bd[s] = d; bi[s] = j; }
                        worst = bd[0]; wslot = 0;
#pragma unroll
                        for (int s = 1; s < KNN; s++)
                            if (bd[s] > worst) { worst = bd[s]; wslot = s; }
                    }
                }
            }
        }
        // exact stop bound: min distance from q to unscanned region
        float b = FLT_MAX;
        if (zlo > 0)        b = fminf(b, q.z - (GMINF + zlo * GH));
        if (zhi < GRID - 1) b = fminf(b, (GMINF + (zhi + 1) * GH) - q.z);
        if (ylo > 0)        b = fminf(b, q.y - (GMINF + ylo * GH));
        if (yhi < GRID - 1) b = fminf(b, (GMINF + (yhi + 1) * GH) - q.y);
        if (xlo > 0)        b = fminf(b, q.x - (GMINF + xlo * GH));
        if (xhi < GRID - 1) b = fminf(b, (GMINF + (xhi + 1) * GH) - q.x);
        if (worst <= b * b) break;
    }

    const int orig = g_sorted_orig[t];
    float sx = 0.f, sy = 0.f, sz = 0.f, qx = 0.f, qy = 0.f, qz = 0.f;
#pragma unroll
    for (int s = 0; s < KNN; s++) {
        int pos = bi[s];
        float4 p = g_pts4[pos];
        g_knn[orig * KNN + s] = g_sorted_orig[pos];
        float rx = p.x - q.x;
        float ry = p.y - q.y;
        float rz = p.z - q.z;
        sx += rx; sy += ry; sz += rz;
        qx = fmaf(rx, rx, qx); qy = fmaf(ry, ry, qy); qz = fmaf(rz, rz, qz);
    }
    const float inv = 1.f / (float)KNN;
    float mx = sx * inv, my = sy * inv, mz = sz * inv;
    g_rel[orig * 6 + 0] = mx;
    g_rel[orig * 6 + 1] = my;
    g_rel[orig * 6 + 2] = mz;
    g_rel[orig * 6 + 3] = sqrtf(fmaxf(qx * inv - mx * mx, 0.f));
    g_rel[orig * 6 + 4] = sqrtf(fmaxf(qy * inv - my * my, 0.f));
    g_rel[orig * 6 + 5] = sqrtf(fmaxf(qz * inv - mz * mz, 0.f));
}

// ---------------- FiLM gamma/beta (depends only on z); one block per layer --
__global__ void film_kernel(const float* __restrict__ z,
                            const float* __restrict__ Wg, const float* __restrict__ bg,
                            const float* __restrict__ Wb, const float* __restrict__ bb) {
    int c = threadIdx.x;  // 192
    int li = blockIdx.x;  // 4
    float ga = bg[li * WID + c];
    float be = bb[li * WID + c];
    for (int k = 0; k < CONDD; k++) {
        float zk = z[k];
        ga = fmaf(zk, Wg[(li * CONDD + k) * WID + c], ga);
        be = fmaf(zk, Wb[(li * CONDD + k) * WID + c], be);
    }
    g_gamma[li * WID + c] = ga;
    g_beta[li * WID + c]  = be;
}

__device__ __forceinline__ float silu(float a) {
    return a / (1.f + expf(-a));
}

// ---------------- prep: fourier PE + concat z + first dense + silu ----------
__global__ void prep_kernel(const float* __restrict__ x, const float* __restrict__ z,
                            const float* __restrict__ B0, const float* __restrict__ B1,
                            const float* __restrict__ B2,
                            const float* __restrict__ Wp, const float* __restrict__ bp,
                            int n) {
    __shared__ float fs[BRP * 120];
    const int row0 = blockIdx.x * BRP;
    const int tid = threadIdx.x;  // 192

    for (int e = tid; e < BRP * IN0; e += 192) {
        int r = e / IN0, i = e % IN0;
        int row = row0 + r;
        float v = 0.f;
        if (row < n) {
            if (i < 48) {
                int g = i >> 4, w = i & 15, col = w & 7;
                const float* B = (g == 0) ? B0 : ((g == 1) ? B1 : B2);
                float x0 = x[row * 3 + 0], x1 = x[row * 3 + 1], x2 = x[row * 3 + 2];
                float dot = fmaf(x0, B[col], fmaf(x1, B[8 + col], x2 * B[16 + col]));
                v = (w < 8) ? sinf(dot) : cosf(dot);
            } else if (i < 51) {
                v = x[row * 3 + (i - 48)];
            } else {
                v = z[i - 51];
            }
        }
        fs[r * 120 + i] = v;
    }
    for (int e = tid; e < BRP * 5; e += 192) {
        int r = e / 5, i = 115 + e % 5;
        fs[r * 120 + i] = 0.f;
    }
    __syncthreads();

    const int c = tid;
    float acc[BRP];
    float b = bp[c];
#pragma unroll
    for (int r = 0; r < BRP; r++) acc[r] = b;

    for (int ic = 0; ic < 28; ic++) {
        int i = ic * 4;
        float w0 = Wp[(i + 0) * WID + c];
        float w1 = Wp[(i + 1) * WID + c];
        float w2 = Wp[(i + 2) * WID + c];
        float w3 = Wp[(i + 3) * WID + c];
#pragma unroll
        for (int r = 0; r < BRP; r++) {
            float4 m = *(const float4*)&fs[r * 120 + i];
            acc[r] = fmaf(m.x, w0, acc[r]);
            acc[r] = fmaf(m.y, w1, acc[r]);
            acc[r] = fmaf(m.z, w2, acc[r]);
            acc[r] = fmaf(m.w, w3, acc[r]);
        }
    }
    for (int i = 112; i < 115; i++) {
        float w0 = Wp[i * WID + c];
#pragma unroll
        for (int r = 0; r < BRP; r++) acc[r] = fmaf(fs[r * 120 + i], w0, acc[r]);
    }

#pragma unroll
    for (int r = 0; r < BRP; r++) {
        int row = row0 + r;
        if (row < n) g_h[0][row * WID + c] = silu(acc[r]);
    }
}

// ---------------- one graph layer: gather+mean, mix GEMM (f32x2), FiLM ------
// mix staged pair-packed: msp[k*SP + 2*pair + half], k = 0..391 (390/391 zero)
__global__ void __launch_bounds__(192) layer_kernel(int src, int li,
                             const float* __restrict__ Wl_all,
                             const float* __restrict__ bl_all,
                             int n) {
    __shared__ float msp[392 * SP];
    const float* __restrict__ hin = g_h[src];
    float* __restrict__ hout = g_h[1 - src];
    const float* __restrict__ Wl = Wl_all + (size_t)li * MIXD * WID;

    const int row0 = blockIdx.x * BRL;
    const int c = threadIdx.x;  // 192
    const float inv = 1.f / (float)KNN;

    for (int r = 0; r < BRL; r++) {
        int row = row0 + r;
        float hv = 0.f, s = 0.f;
        if (row < n) {
            hv = hin[(size_t)row * WID + c];
#pragma unroll
            for (int j = 0; j < KNN; j++) {
                int nb = g_knn[row * KNN + j];
                s += hin[(size_t)nb * WID + c];
            }
        }
        int po = (r >> 1) * 2 + (r & 1);
        msp[c * SP + po]         = hv;
        msp[(192 + c) * SP + po] = s * inv;
    }
    for (int e = c; e < BRL * 8; e += 192) {
        int r = e >> 3, i2 = e & 7;
        int row = row0 + r;
        float v = (i2 < 6 && row < n) ? g_rel[row * 6 + i2] : 0.f;
        msp[(384 + i2) * SP + (r >> 1) * 2 + (r & 1)] = v;
    }
    __syncthreads();

    unsigned long long acc[NPAIR];
    {
        unsigned long long b2 = pk2(bl_all[li * WID + c]);
#pragma unroll
        for (int p = 0; p < NPAIR; p++) acc[p] = b2;
    }

    // 98 iterations x 4 k-steps, weight prefetch double-buffer
    float wc0 = Wl[0 * WID + c];
    float wc1 = Wl[1 * WID + c];
    float wc2 = Wl[2 * WID + c];
    float wc3 = Wl[3 * WID + c];
    for (int ic = 0; ic < 98; ic++) {
        int i = ic * 4;
        float n0 = 0.f, n1 = 0.f, n2 = 0.f, n3 = 0.f;
        if (ic < 97) {
            n0 = (i + 4 < MIXD) ? Wl[(i + 4) * WID + c] : 0.f;
            n1 = (i + 5 < MIXD) ? Wl[(i + 5) * WID + c] : 0.f;
            n2 = (i + 6 < MIXD) ? Wl[(i + 6) * WID + c] : 0.f;
            n3 = (i + 7 < MIXD) ? Wl[(i + 7) * WID + c] : 0.f;
        }
#pragma unroll
        for (int kk = 0; kk < 4; kk++) {
            unsigned long long w2 = pk2(kk == 0 ? wc0 : (kk == 1 ? wc1 : (kk == 2 ? wc2 : wc3)));
            const ulonglong2* mp = (const ulonglong2*)&msp[(i + kk) * SP];
#pragma unroll
            for (int q = 0; q < 6; q++) {
                ulonglong2 mv = mp[q];
                fma2(acc[2 * q],     mv.x, w2);
                fma2(acc[2 * q + 1], mv.y, w2);
            }
        }
        wc0 = n0; wc1 = n1; wc2 = n2; wc3 = n3;
    }

    const float ga = g_gamma[li * WID + c];
    const float be = g_beta[li * WID + c];
#pragma unroll
    for (int p = 0; p < NPAIR; p++) {
        float a0, a1;
        unpk2(acc[p], a0, a1);
        int row = row0 + 2 * p;
        if (row < n)     hout[(size_t)row * WID + c]       = fmaf(silu(a0), ga, be);
        if (row + 1 < n) hout[(size_t)(row + 1) * WID + c] = fmaf(silu(a1), ga, be);
    }
}

// ---------------- output head: (h @ Wout + bout) * 0.01 ---------------------
__global__ void out_kernel(const float* __restrict__ Wout,
                           const float* __restrict__ bout,
                           float* __restrict__ out, int n) {
    const float* __restrict__ hin = g_h[0];  // after 4 layers: 0->1->0->1->0
    int gtid = blockIdx.x * blockDim.x + threadIdx.x;
    int warp = gtid >> 5;
    int lane = threadIdx.x & 31;
    if (warp >= n) return;
    float a0 = 0.f, a1 = 0.f, a2 = 0.f;
    for (int i = lane; i < WID; i += 32) {
        float h = hin[warp * WID + i];
        a0 = fmaf(h, Wout[i * 3 + 0], a0);
        a1 = fmaf(h, Wout[i * 3 + 1], a1);
        a2 = fmaf(h, Wout[i * 3 + 2], a2);
    }
#pragma unroll
    for (int o = 16; o; o >>= 1) {
        a0 += __shfl_down_sync(0xffffffffu, a0, o);
        a1 += __shfl_down_sync(0xffffffffu, a1, o);
        a2 += __shfl_down_sync(0xffffffffu, a2, o);
    }
    if (lane == 0) {
        out[warp * 3 + 0] = (a0 + bout[0]) * 0.01f;
        out[warp * 3 + 1] = (a1 + bout[1]) * 0.01f;
        out[warp * 3 + 2] = (a2 + bout[2]) * 0.01f;
    }
}

// ---------------- launch -----------------------------------------------------
extern "C" void kernel_launch(void* const* d_in, const int* in_sizes, int n_in,
                              void* d_out, int out_size) {
    const float* x    = (const float*)d_in[0];
    const float* z    = (const float*)d_in[1];
    const float* B0   = (const float*)d_in[2];
    const float* B1   = (const float*)d_in[3];
    const float* B2   = (const float*)d_in[4];
    const float* Wp   = (const float*)d_in[5];
    const float* bp   = (const float*)d_in[6];
    const float* Wl   = (const float*)d_in[7];
    const float* bl   = (const float*)d_in[8];
    const float* Wg   = (const float*)d_in[9];
    const float* bg   = (const float*)d_in[10];
    const float* Wb   = (const float*)d_in[11];
    const float* bb   = (const float*)d_in[12];
    const float* Wout = (const float*)d_in[13];
    const float* bout = (const float*)d_in[14];
    float* out = (float*)d_out;

    const int n = in_sizes[0] / 3;

    // spatial-grid kNN (32^3 cells)
    grid_zero_kernel<<<(CELLS + 255) / 256, 256>>>();
    grid_hist_kernel<<<(n + 255) / 256, 256>>>(x, n);
    grid_scan_kernel<<<1, 1024>>>();
    grid_scatter_kernel<<<(n + 255) / 256, 256>>>(x, n);
    knn_search_kernel<<<(n + 127) / 128, 128>>>(n);

    film_kernel<<<NL, WID>>>(z, Wg, bg, Wb, bb);
    prep_kernel<<<(n + BRP - 1) / BRP, WID>>>(x, z, B0, B1, B2, Wp, bp, n);

    int src = 0;
    for (int li = 0; li < NL; li++) {
        layer_kernel<<<(n + BRL - 1) / BRL, WID>>>(src, li, Wl, bl, n);
        src = 1 - src;
    }

    out_kernel<<<(n * 32 + 255) / 256, 256>>>(Wout, bout, out, n);
}

// round 9
// speedup vs baseline: 1.8961x; 1.0452x over previous
#include <cuda_runtime.h>
#include <stdint.h>
#include <math.h>
#include <float.h>

#define NMAX   32768
#define KNN    12
#define WID    192
#define CONDD  64
#define IN0    115      // 51 PE + 64 cond
#define MIXD   390      // 192 + 192 + 6
#define NL     4
#define BRP    16       // rows per block, prep
#define BRL    24       // rows per block, layer

#define GRID   32
#define CELLS  (GRID * GRID * GRID)
#define GMINF  (-4.0f)
#define GH     0.25f
#define GINVH  4.0f

// ---------------- scratch (device globals; no allocations allowed) ----------
// all per-point arrays live in SORTED (spatially clustered) index space
__device__ int    g_knn[NMAX * KNN];
__device__ float  g_rel[NMAX * 6];
__device__ float  g_h[2][NMAX * WID];
__device__ float  g_gamma[NL * WID];
__device__ float  g_beta[NL * WID];

__device__ int    g_cnt[CELLS];
__device__ int    g_start[CELLS + 1];
__device__ int    g_cell[NMAX];
__device__ int    g_rank[NMAX];
__device__ float4 g_pts4[NMAX];       // sorted coords + |p|^2
__device__ int    g_sorted_orig[NMAX];

// ---------------- grid build -------------------------------------------------
__device__ __forceinline__ int cell_coord(float v) {
    int c = (int)floorf((v - GMINF) * GINVH);
    return min(GRID - 1, max(0, c));
}

__global__ void grid_zero_kernel() {
    int i = blockIdx.x * blockDim.x + threadIdx.x;
    if (i < CELLS) g_cnt[i] = 0;
}

__global__ void grid_hist_kernel(const float* __restrict__ x, int n) {
    int i = blockIdx.x * blockDim.x + threadIdx.x;
    if (i >= n) return;
    int cx = cell_coord(x[i * 3 + 0]);
    int cy = cell_coord(x[i * 3 + 1]);
    int cz = cell_coord(x[i * 3 + 2]);
    int c = (cz * GRID + cy) * GRID + cx;
    g_cell[i] = c;
    g_rank[i] = atomicAdd(&g_cnt[c], 1);
}

__global__ void grid_scan_kernel() {  // single block, 1024 threads, 32 cells each
    __shared__ int sh[1024];
    int tid = threadIdx.x;
    int base = tid * 32;
    int s = 0;
    for (int k = 0; k < 32; k++) s += g_cnt[base + k];
    sh[tid] = s;
    __syncthreads();
    for (int off = 1; off < 1024; off <<= 1) {
        int v = (tid >= off) ? sh[tid - off] : 0;
        __syncthreads();
        sh[tid] += v;
        __syncthreads();
    }
    int run = sh[tid] - s;  // exclusive base
    for (int k = 0; k < 32; k++) {
        g_start[base + k] = run;
        run += g_cnt[base + k];
    }
    if (tid == 1023) g_start[CELLS] = sh[1023];
}

__global__ void grid_scatter_kernel(const float* __restrict__ x, int n) {
    int i = blockIdx.x * blockDim.x + threadIdx.x;
    if (i >= n) return;
    float px = x[i * 3 + 0], py = x[i * 3 + 1], pz = x[i * 3 + 2];
    int pos = g_start[g_cell[i]] + g_rank[i];
    g_pts4[pos] = make_float4(px, py, pz, fmaf(px, px, fmaf(py, py, pz * pz)));
    g_sorted_orig[pos] = i;
}

// ---------------- kNN search: expanding shells with exact stop bound --------
// emits neighbor indices in SORTED space (row t's data stored at row t)
__global__ void knn_search_kernel(int n) {
    const int t = blockIdx.x * blockDim.x + threadIdx.x;
    if (t >= n) return;
    const float4 q = g_pts4[t];
    const float qsq = q.w;
    const int cx = cell_coord(q.x);
    const int cy = cell_coord(q.y);
    const int cz = cell_coord(q.z);

    float bd[KNN];
    int   bi[KNN];
#pragma unroll
    for (int s = 0; s < KNN; s++) { bd[s] = 1e30f; bi[s] = 0; }
    float worst = 1e30f;
    int   wslot = 0;

    for (int r = 0; r < GRID; r++) {
        const int zlo = max(cz - r, 0), zhi = min(cz + r, GRID - 1);
        const int ylo = max(cy - r, 0), yhi = min(cy + r, GRID - 1);
        const int xlo = max(cx - r, 0), xhi = min(cx + r, GRID - 1);
        for (int iz = zlo; iz <= zhi; iz++) {
            const bool zedge = (iz == cz - r) || (iz == cz + r);
            for (int iy = ylo; iy <= yhi; iy++) {
                const bool yedge = (iy == cy - r) || (iy == cy + r);
                const int rowc = (iz * GRID + iy) * GRID;
                int j0, j1;
                if (zedge || yedge) {
                    j0 = g_start[rowc + xlo];
                    j1 = g_start[rowc + xhi + 1];
                } else {
                    j0 = 0; j1 = 0;
                    if (cx - r >= 0) {
                        int c = rowc + (cx - r);
                        j0 = g_start[c]; j1 = g_start[c + 1];
                    }
                    if (cx + r <= GRID - 1) {
                        int c = rowc + (cx + r);
                        int a0 = g_start[c], a1 = g_start[c + 1];
                        for (int j = a0; j < a1; j++) {
                            float4 p = g_pts4[j];
                            float d = qsq + p.w
                                    - 2.f * fmaf(q.x, p.x, fmaf(q.y, p.y, q.z * p.z));
                            if (d < worst && j != t) {
#pragma unroll
                                for (int s = 0; s < KNN; s++)
                                    if (s == wslot) { bd[s] = d; bi[s] = j; }
                                worst = bd[0]; wslot = 0;
#pragma unroll
                                for (int s = 1; s < KNN; s++)
                                    if (bd[s] > worst) { worst = bd[s]; wslot = s; }
                            }
                        }
                    }
                }
                for (int j = j0; j < j1; j++) {
                    float4 p = g_pts4[j];
                    float d = qsq + p.w
                            - 2.f * fmaf(q.x, p.x, fmaf(q.y, p.y, q.z * p.z));
                    if (d < worst && j != t) {
#pragma unroll
                        for (int s = 0; s < KNN; s++)
                            if (s == wslot) { bd[s] = d; bi[s] = j; }
                        worst = bd[0]; wslot = 0;
#pragma unroll
                        for (int s = 1; s < KNN; s++)
                            if (bd[s] > worst) { worst = bd[s]; wslot = s; }
                    }
                }
            }
        }
        // exact stop bound: min distance from q to unscanned region
        float b = FLT_MAX;
        if (zlo > 0)        b = fminf(b, q.z - (GMINF + zlo * GH));
        if (zhi < GRID - 1) b = fminf(b, (GMINF + (zhi + 1) * GH) - q.z);
        if (ylo > 0)        b = fminf(b, q.y - (GMINF + ylo * GH));
        if (yhi < GRID - 1) b = fminf(b, (GMINF + (yhi + 1) * GH) - q.y);
        if (xlo > 0)        b = fminf(b, q.x - (GMINF + xlo * GH));
        if (xhi < GRID - 1) b = fminf(b, (GMINF + (xhi + 1) * GH) - q.x);
        if (worst <= b * b) break;
    }

    float sx = 0.f, sy = 0.f, sz = 0.f, qx = 0.f, qy = 0.f, qz = 0.f;
#pragma unroll
    for (int s = 0; s < KNN; s++) {
        int pos = bi[s];
        float4 p = g_pts4[pos];
        g_knn[t * KNN + s] = pos;                 // sorted-space neighbor id
        float rx = p.x - q.x;
        float ry = p.y - q.y;
        float rz = p.z - q.z;
        sx += rx; sy += ry; sz += rz;
        qx = fmaf(rx, rx, qx); qy = fmaf(ry, ry, qy); qz = fmaf(rz, rz, qz);
    }
    const float inv = 1.f / (float)KNN;
    float mx = sx * inv, my = sy * inv, mz = sz * inv;
    g_rel[t * 6 + 0] = mx;
    g_rel[t * 6 + 1] = my;
    g_rel[t * 6 + 2] = mz;
    g_rel[t * 6 + 3] = sqrtf(fmaxf(qx * inv - mx * mx, 0.f));
    g_rel[t * 6 + 4] = sqrtf(fmaxf(qy * inv - my * my, 0.f));
    g_rel[t * 6 + 5] = sqrtf(fmaxf(qz * inv - mz * mz, 0.f));
}

// ---------------- FiLM gamma/beta (depends only on z); one block per layer --
__global__ void film_kernel(const float* __restrict__ z,
                            const float* __restrict__ Wg, const float* __restrict__ bg,
                            const float* __restrict__ Wb, const float* __restrict__ bb) {
    int c = threadIdx.x;  // 192
    int li = blockIdx.x;  // 4
    float ga = bg[li * WID + c];
    float be = bb[li * WID + c];
    for (int k = 0; k < CONDD; k++) {
        float zk = z[k];
        ga = fmaf(zk, Wg[(li * CONDD + k) * WID + c], ga);
        be = fmaf(zk, Wb[(li * CONDD + k) * WID + c], be);
    }
    g_gamma[li * WID + c] = ga;
    g_beta[li * WID + c]  = be;
}

__device__ __forceinline__ float silu(float a) {
    return a / (1.f + expf(-a));
}

// ---------------- prep: fourier PE + concat z + first dense + silu ----------
// operates in sorted space: coords from g_pts4
__global__ void prep_kernel(const float* __restrict__ z,
                            const float* __restrict__ B0, const float* __restrict__ B1,
                            const float* __restrict__ B2,
                            const float* __restrict__ Wp, const float* __restrict__ bp,
                            int n) {
    __shared__ float fs[BRP * 120];
    const int row0 = blockIdx.x * BRP;
    const int tid = threadIdx.x;  // 192

    for (int e = tid; e < BRP * IN0; e += 192) {
        int r = e / IN0, i = e % IN0;
        int row = row0 + r;
        float v = 0.f;
        if (row < n) {
            float4 p = g_pts4[row];
            if (i < 48) {
                int g = i >> 4, w = i & 15, col = w & 7;
                const float* B = (g == 0) ? B0 : ((g == 1) ? B1 : B2);
                float dot = fmaf(p.x, B[col], fmaf(p.y, B[8 + col], p.z * B[16 + col]));
                v = (w < 8) ? sinf(dot) : cosf(dot);
            } else if (i < 51) {
                v = (i == 48) ? p.x : ((i == 49) ? p.y : p.z);
            } else {
                v = z[i - 51];
            }
        }
        fs[r * 120 + i] = v;
    }
    for (int e = tid; e < BRP * 5; e += 192) {
        int r = e / 5, i = 115 + e % 5;
        fs[r * 120 + i] = 0.f;
    }
    __syncthreads();

    const int c = tid;
    float acc[BRP];
    float b = bp[c];
#pragma unroll
    for (int r = 0; r < BRP; r++) acc[r] = b;

    for (int ic = 0; ic < 28; ic++) {
        int i = ic * 4;
        float w0 = Wp[(i + 0) * WID + c];
        float w1 = Wp[(i + 1) * WID + c];
        float w2 = Wp[(i + 2) * WID + c];
        float w3 = Wp[(i + 3) * WID + c];
#pragma unroll
        for (int r = 0; r < BRP; r++) {
            float4 m = *(const float4*)&fs[r * 120 + i];
            acc[r] = fmaf(m.x, w0, acc[r]);
            acc[r] = fmaf(m.y, w1, acc[r]);
            acc[r] = fmaf(m.z, w2, acc[r]);
            acc[r] = fmaf(m.w, w3, acc[r]);
        }
    }
    for (int i = 112; i < 115; i++) {
        float w0 = Wp[i * WID + c];
#pragma unroll
        for (int r = 0; r < BRP; r++) acc[r] = fmaf(fs[r * 120 + i], w0, acc[r]);
    }

#pragma unroll
    for (int r = 0; r < BRP; r++) {
        int row = row0 + r;
        if (row < n) g_h[0][(size_t)row * WID + c] = silu(acc[r]);
    }
}

// ---------------- one graph layer: gather+mean, mix GEMM, silu, FiLM --------
__global__ void __launch_bounds__(192) layer_kernel(int src, int li,
                             const float* __restrict__ Wl_all,
                             const float* __restrict__ bl_all,
                             int n) {
    __shared__ float ms[BRL * 392];  // [h(192) | agg(192) | rel(6) | pad(2)]
    const float* __restrict__ hin = g_h[src];
    float* __restrict__ hout = g_h[1 - src];
    const float* __restrict__ Wl = Wl_all + (size_t)li * MIXD * WID;

    const int row0 = blockIdx.x * BRL;
    const int c = threadIdx.x;  // 192
    const float inv = 1.f / (float)KNN;

    for (int r = 0; r < BRL; r++) {
        int row = row0 + r;
        float hv = 0.f, s = 0.f;
        if (row < n) {
            hv = hin[(size_t)row * WID + c];
            const int4* nbp = (const int4*)&g_knn[row * KNN];
            int4 na = nbp[0], nb = nbp[1], nc = nbp[2];
            int ids[KNN] = {na.x, na.y, na.z, na.w, nb.x, nb.y, nb.z, nb.w,
                            nc.x, nc.y, nc.z, nc.w};
#pragma unroll
            for (int j = 0; j < KNN; j++)
                s += hin[(size_t)ids[j] * WID + c];
        }
        ms[r * 392 + c]       = hv;
        ms[r * 392 + 192 + c] = s * inv;
    }
    for (int e = c; e < BRL * 8; e += 192) {
        int r = e / 8, i = e % 8;
        int row = row0 + r;
        ms[r * 392 + 384 + i] = (i < 6 && row < n) ? g_rel[row * 6 + i] : 0.f;
    }
    __syncthreads();

    float acc[BRL];
    float b = bl_all[li * WID + c];
#pragma unroll
    for (int r = 0; r < BRL; r++) acc[r] = b;

    // double-buffered weight registers to cover LDG latency
    float w0 = Wl[0 * WID + c];
    float w1 = Wl[1 * WID + c];
    float w2 = Wl[2 * WID + c];
    float w3 = Wl[3 * WID + c];
    for (int ic = 0; ic < 97; ic++) {  // 388 of 390
        int i = ic * 4;
        float n0 = 0.f, n1 = 0.f, n2 = 0.f, n3 = 0.f;
        if (ic < 96) {
            n0 = Wl[(i + 4) * WID + c];
            n1 = Wl[(i + 5) * WID + c];
            n2 = Wl[(i + 6) * WID + c];
            n3 = Wl[(i + 7) * WID + c];
        }
#pragma unroll
        for (int r = 0; r < BRL; r++) {
            float4 m = *(const float4*)&ms[r * 392 + i];
            acc[r] = fmaf(m.x, w0, acc[r]);
            acc[r] = fmaf(m.y, w1, acc[r]);
            acc[r] = fmaf(m.z, w2, acc[r]);
            acc[r] = fmaf(m.w, w3, acc[r]);
        }
        w0 = n0; w1 = n1; w2 = n2; w3 = n3;
    }
    for (int i = 388; i < 390; i++) {
        float wv = Wl[i * WID + c];
#pragma unroll
        for (int r = 0; r < BRL; r++) acc[r] = fmaf(ms[r * 392 + i], wv, acc[r]);
    }

    const float ga = g_gamma[li * WID + c];
    const float be = g_beta[li * WID + c];
#pragma unroll
    for (int r = 0; r < BRL; r++) {
        int row = row0 + r;
        if (row < n) hout[(size_t)row * WID + c] = fmaf(silu(acc[r]), ga, be);
    }
}

// ---------------- output head: (h @ Wout + bout) * 0.01, scatter to orig ----
__global__ void out_kernel(const float* __restrict__ Wout,
                           const float* __restrict__ bout,
                           float* __restrict__ out, int n) {
    const float* __restrict__ hin = g_h[0];  // after 4 layers: 0->1->0->1->0
    int gtid = blockIdx.x * blockDim.x + threadIdx.x;
    int warp = gtid >> 5;
    int lane = threadIdx.x & 31;
    if (warp >= n) return;
    float a0 = 0.f, a1 = 0.f, a2 = 0.f;
    for (int i = lane; i < WID; i += 32) {
        float h = hin[(size_t)warp * WID + i];
        a0 = fmaf(h, Wout[i * 3 + 0], a0);
        a1 = fmaf(h, Wout[i * 3 + 1], a1);
        a2 = fmaf(h, Wout[i * 3 + 2], a2);
    }
#pragma unroll
    for (int o = 16; o; o >>= 1) {
        a0 += __shfl_down_sync(0xffffffffu, a0, o);
        a1 += __shfl_down_sync(0xffffffffu, a1, o);
        a2 += __shfl_down_sync(0xffffffffu, a2, o);
    }
    if (lane == 0) {
        int orig = g_sorted_orig[warp];
        out[orig * 3 + 0] = (a0 + bout[0]) * 0.01f;
        out[orig * 3 + 1] = (a1 + bout[1]) * 0.01f;
        out[orig * 3 + 2] = (a2 + bout[2]) * 0.01f;
    }
}

// ---------------- launch -----------------------------------------------------
extern "C" void kernel_launch(void* const* d_in, const int* in_sizes, int n_in,
                              void* d_out, int out_size) {
    const float* x    = (const float*)d_in[0];
    const float* z    = (const float*)d_in[1];
    const float* B0   = (const float*)d_in[2];
    const float* B1   = (const float*)d_in[3];
    const float* B2   = (const float*)d_in[4];
    const float* Wp   = (const float*)d_in[5];
    const float* bp   = (const float*)d_in[6];
    const float* Wl   = (const float*)d_in[7];
    const float* bl   = (const float*)d_in[8];
    const float* Wg   = (const float*)d_in[9];
    const float* bg   = (const float*)d_in[10];
    const float* Wb   = (const float*)d_in[11];
    const float* bb   = (const float*)d_in[12];
    const float* Wout = (const float*)d_in[13];
    const float* bout = (const float*)d_in[14];
    float* out = (float*)d_out;

    const int n = in_sizes[0] / 3;

    // spatial-grid kNN (32^3 cells), sorted index space
    grid_zero_kernel<<<(CELLS + 255) / 256, 256>>>();
    grid_hist_kernel<<<(n + 255) / 256, 256>>>(x, n);
    grid_scan_kernel<<<1, 1024>>>();
    grid_scatter_kernel<<<(n + 255) / 256, 256>>>(x, n);
    knn_search_kernel<<<(n + 127) / 128, 128>>>(n);

    film_kernel<<<NL, WID>>>(z, Wg, bg, Wb, bb);
    prep_kernel<<<(n + BRP - 1) / BRP, WID>>>(z, B0, B1, B2, Wp, bp, n);

    int src = 0;
    for (int li = 0; li < NL; li++) {
        layer_kernel<<<(n + BRL - 1) / BRL, WID>>>(src, li, Wl, bl, n);
        src = 1 - src;
    }

    out_kernel<<<(n * 32 + 255) / 256, 256>>>(Wout, bout, out, n);
}

// round 10
// speedup vs baseline: 2.4193x; 1.2760x over previous
#include <cuda_runtime.h>
#include <cuda_bf16.h>
#include <stdint.h>
#include <math.h>
#include <float.h>

#define NMAX   32768
#define KNN    12
#define WID    192
#define CONDD  64
#define IN0    115      // 51 PE + 64 cond
#define MIXD   390      // 192 + 192 + 6
#define NL     4
#define BRP    16       // rows per block, prep

#define GRID   32
#define CELLS  (GRID * GRID * GRID)
#define GMINF  (-4.0f)
#define GH     0.25f
#define GINVH  4.0f

// GEMM constants
#define GEMM_M   64
#define SLAB     6144                 // u32 per k-chunk B slab (48nt*2split*64)
#define LI_WORDS 73728                // u32 per layer of packed B frags (12 slabs)
#define SA_STRIDE 196
#define SA_WORDS (64 * SA_STRIDE)     // 12544
#define SM_WORDS (SA_WORDS + 2 * SLAB)   // 24832 u32 = 99328 B

// ---------------- scratch (device globals; no allocations allowed) ----------
// all per-point arrays live in SORTED (spatially clustered) index space
__device__ int      g_knn[NMAX * KNN];
__device__ float    g_rel[NMAX * 6];
__device__ uint32_t g_hbf[2][NMAX * WID];   // h packed as (bf16 hi<<16 | bf16 lo)
__device__ float    g_P[NMAX * WID];
__device__ float    g_Yv[NMAX * WID];
__device__ float    g_gamma[NL * WID];
__device__ float    g_beta[NL * WID];
__device__ uint32_t g_Bfrag[NL * LI_WORDS]; // weights in mma-fragment-linear order

__device__ int    g_cnt[CELLS];
__device__ int    g_start[CELLS + 1];
__device__ int    g_cell[NMAX];
__device__ int    g_rank[NMAX];
__device__ float4 g_pts4[NMAX];
__device__ int    g_sorted_orig[NMAX];

// ---------------- helpers -----------------------------------------------------
__device__ __forceinline__ uint32_t pack_hl(float v) {
    __nv_bfloat16 h = __float2bfloat16(v);
    float lof = v - __bfloat162float(h);
    __nv_bfloat16 l = __float2bfloat16(lof);
    return ((uint32_t)__bfloat16_as_ushort(h) << 16) | (uint32_t)__bfloat16_as_ushort(l);
}
__device__ __forceinline__ float unpack_hl(uint32_t u) {
    return __bfloat162float(__ushort_as_bfloat16((unsigned short)(u >> 16)))
         + __bfloat162float(__ushort_as_bfloat16((unsigned short)(u & 0xFFFFu)));
}

#define MMA4(cc, a0, a1, a2, a3, b0, b1)                                     \
    asm volatile(                                                            \
        "mma.sync.aligned.m16n8k16.row.col.f32.bf16.bf16.f32 "               \
        "{%0,%1,%2,%3}, {%4,%5,%6,%7}, {%8,%9}, {%0,%1,%2,%3};"              \
        : "+f"(cc[0]), "+f"(cc[1]), "+f"(cc[2]), "+f"(cc[3])                 \
        : "r"(a0), "r"(a1), "r"(a2), "r"(a3), "r"(b0), "r"(b1))

// ---------------- grid build -------------------------------------------------
__device__ __forceinline__ int cell_coord(float v) {
    int c = (int)floorf((v - GMINF) * GINVH);
    return min(GRID - 1, max(0, c));
}

__global__ void grid_zero_kernel() {
    int i = blockIdx.x * blockDim.x + threadIdx.x;
    if (i < CELLS) g_cnt[i] = 0;
}

__global__ void grid_hist_kernel(const float* __restrict__ x, int n) {
    int i = blockIdx.x * blockDim.x + threadIdx.x;
    if (i >= n) return;
    int cx = cell_coord(x[i * 3 + 0]);
    int cy = cell_coord(x[i * 3 + 1]);
    int cz = cell_coord(x[i * 3 + 2]);
    int c = (cz * GRID + cy) * GRID + cx;
    g_cell[i] = c;
    g_rank[i] = atomicAdd(&g_cnt[c], 1);
}

__global__ void grid_scan_kernel() {
    __shared__ int sh[1024];
    int tid = threadIdx.x;
    int base = tid * 32;
    int s = 0;
    for (int k = 0; k < 32; k++) s += g_cnt[base + k];
    sh[tid] = s;
    __syncthreads();
    for (int off = 1; off < 1024; off <<= 1) {
        int v = (tid >= off) ? sh[tid - off] : 0;
        __syncthreads();
        sh[tid] += v;
        __syncthreads();
    }
    int run = sh[tid] - s;
    for (int k = 0; k < 32; k++) {
        g_start[base + k] = run;
        run += g_cnt[base + k];
    }
    if (tid == 1023) g_start[CELLS] = sh[1023];
}

__global__ void grid_scatter_kernel(const float* __restrict__ x, int n) {
    int i = blockIdx.x * blockDim.x + threadIdx.x;
    if (i >= n) return;
    float px = x[i * 3 + 0], py = x[i * 3 + 1], pz = x[i * 3 + 2];
    int pos = g_start[g_cell[i]] + g_rank[i];
    g_pts4[pos] = make_float4(px, py, pz, fmaf(px, px, fmaf(py, py, pz * pz)));
    g_sorted_orig[pos] = i;
}

// ---------------- kNN search: expanding shells with exact stop bound --------
__global__ void knn_search_kernel(int n) {
    const int t = blockIdx.x * blockDim.x + threadIdx.x;
    if (t >= n) return;
    const float4 q = g_pts4[t];
    const float qsq = q.w;
    const int cx = cell_coord(q.x);
    const int cy = cell_coord(q.y);
    const int cz = cell_coord(q.z);

    float bd[KNN];
    int   bi[KNN];
#pragma unroll
    for (int s = 0; s < KNN; s++) { bd[s] = 1e30f; bi[s] = 0; }
    float worst = 1e30f;
    int   wslot = 0;

    for (int r = 0; r < GRID; r++) {
        const int zlo = max(cz - r, 0), zhi = min(cz + r, GRID - 1);
        const int ylo = max(cy - r, 0), yhi = min(cy + r, GRID - 1);
        const int xlo = max(cx - r, 0), xhi = min(cx + r, GRID - 1);
        for (int iz = zlo; iz <= zhi; iz++) {
            const bool zedge = (iz == cz - r) || (iz == cz + r);
            for (int iy = ylo; iy <= yhi; iy++) {
                const bool yedge = (iy == cy - r) || (iy == cy + r);
                const int rowc = (iz * GRID + iy) * GRID;
                int j0, j1;
                if (zedge || yedge) {
                    j0 = g_start[rowc + xlo];
                    j1 = g_start[rowc + xhi + 1];
                } else {
                    j0 = 0; j1 = 0;
                    if (cx - r >= 0) {
                        int c = rowc + (cx - r);
                        j0 = g_start[c]; j1 = g_start[c + 1];
                    }
                    if (cx + r <= GRID - 1) {
                        int c = rowc + (cx + r);
                        int a0 = g_start[c], a1 = g_start[c + 1];
                        for (int j = a0; j < a1; j++) {
                            float4 p = g_pts4[j];
                            float d = qsq + p.w
                                    - 2.f * fmaf(q.x, p.x, fmaf(q.y, p.y, q.z * p.z));
                            if (d < worst && j != t) {
#pragma unroll
                                for (int s = 0; s < KNN; s++)
                                    if (s == wslot) { bd[s] = d; bi[s] = j; }
                                worst = bd[0]; wslot = 0;
#pragma unroll
                                for (int s = 1; s < KNN; s++)
                                    if (bd[s] > worst) { worst = bd[s]; wslot = s; }
                            }
                        }
                    }
                }
                for (int j = j0; j < j1; j++) {
                    float4 p = g_pts4[j];
                    float d = qsq + p.w
                            - 2.f * fmaf(q.x, p.x, fmaf(q.y, p.y, q.z * p.z));
                    if (d < worst && j != t) {
#pragma unroll
                        for (int s = 0; s < KNN; s++)
                            if (s == wslot) { bd[s] = d; bi[s] = j; }
                        worst = bd[0]; wslot = 0;
#pragma unroll
                        for (int s = 1; s < KNN; s++)
                            if (bd[s] > worst) { worst = bd[s]; wslot = s; }
                    }
                }
            }
        }
        float b = FLT_MAX;
        if (zlo > 0)        b = fminf(b, q.z - (GMINF + zlo * GH));
        if (zhi < GRID - 1) b = fminf(b, (GMINF + (zhi + 1) * GH) - q.z);
        if (ylo > 0)        b = fminf(b, q.y - (GMINF + ylo * GH));
        if (yhi < GRID - 1) b = fminf(b, (GMINF + (yhi + 1) * GH) - q.y);
        if (xlo > 0)        b = fminf(b, q.x - (GMINF + xlo * GH));
        if (xhi < GRID - 1) b = fminf(b, (GMINF + (xhi + 1) * GH) - q.x);
        if (worst <= b * b) break;
    }

    float sx = 0.f, sy = 0.f, sz = 0.f, qx = 0.f, qy = 0.f, qz = 0.f;
#pragma unroll
    for (int s = 0; s < KNN; s++) {
        int pos = bi[s];
        float4 p = g_pts4[pos];
        g_knn[t * KNN + s] = pos;
        float rx = p.x - q.x;
        float ry = p.y - q.y;
        float rz = p.z - q.z;
        sx += rx; sy += ry; sz += rz;
        qx = fmaf(rx, rx, qx); qy = fmaf(ry, ry, qy); qz = fmaf(rz, rz, qz);
    }
    const float inv = 1.f / (float)KNN;
    float mx = sx * inv, my = sy * inv, mz = sz * inv;
    g_rel[t * 6 + 0] = mx;
    g_rel[t * 6 + 1] = my;
    g_rel[t * 6 + 2] = mz;
    g_rel[t * 6 + 3] = sqrtf(fmaxf(qx * inv - mx * mx, 0.f));
    g_rel[t * 6 + 4] = sqrtf(fmaxf(qy * inv - my * my, 0.f));
    g_rel[t * 6 + 5] = sqrtf(fmaxf(qz * inv - mz * mz, 0.f));
}

// ---------------- FiLM gamma/beta -------------------------------------------
__global__ void film_kernel(const float* __restrict__ z,
                            const float* __restrict__ Wg, const float* __restrict__ bg,
                            const float* __restrict__ Wb, const float* __restrict__ bb) {
    int c = threadIdx.x;
    int li = blockIdx.x;
    float ga = bg[li * WID + c];
    float be = bb[li * WID + c];
    for (int k = 0; k < CONDD; k++) {
        float zk = z[k];
        ga = fmaf(zk, Wg[(li * CONDD + k) * WID + c], ga);
        be = fmaf(zk, Wb[(li * CONDD + k) * WID + c], be);
    }
    g_gamma[li * WID + c] = ga;
    g_beta[li * WID + c]  = be;
}

__device__ __forceinline__ float silu(float a) {
    return a / (1.f + expf(-a));
}

// ---------------- prep: fourier PE + concat z + first dense + silu ----------
__global__ void prep_kernel(const float* __restrict__ z,
                            const float* __restrict__ B0, const float* __restrict__ B1,
                            const float* __restrict__ B2,
                            const float* __restrict__ Wp, const float* __restrict__ bp,
                            int n) {
    __shared__ float fs[BRP * 120];
    const int row0 = blockIdx.x * BRP;
    const int tid = threadIdx.x;  // 192

    for (int e = tid; e < BRP * IN0; e += 192) {
        int r = e / IN0, i = e % IN0;
        int row = row0 + r;
        float v = 0.f;
        if (row < n) {
            float4 p = g_pts4[row];
            if (i < 48) {
                int g = i >> 4, w = i & 15, col = w & 7;
                const float* B = (g == 0) ? B0 : ((g == 1) ? B1 : B2);
                float dot = fmaf(p.x, B[col], fmaf(p.y, B[8 + col], p.z * B[16 + col]));
                v = (w < 8) ? sinf(dot) : cosf(dot);
            } else if (i < 51) {
                v = (i == 48) ? p.x : ((i == 49) ? p.y : p.z);
            } else {
                v = z[i - 51];
            }
        }
        fs[r * 120 + i] = v;
    }
    for (int e = tid; e < BRP * 5; e += 192) {
        int r = e / 5, i = 115 + e % 5;
        fs[r * 120 + i] = 0.f;
    }
    __syncthreads();

    const int c = tid;
    float acc[BRP];
    float b = bp[c];
#pragma unroll
    for (int r = 0; r < BRP; r++) acc[r] = b;

    for (int ic = 0; ic < 28; ic++) {
        int i = ic * 4;
        float w0 = Wp[(i + 0) * WID + c];
        float w1 = Wp[(i + 1) * WID + c];
        float w2 = Wp[(i + 2) * WID + c];
        float w3 = Wp[(i + 3) * WID + c];
#pragma unroll
        for (int r = 0; r < BRP; r++) {
            float4 m = *(const float4*)&fs[r * 120 + i];
            acc[r] = fmaf(m.x, w0, acc[r]);
            acc[r] = fmaf(m.y, w1, acc[r]);
            acc[r] = fmaf(m.z, w2, acc[r]);
            acc[r] = fmaf(m.w, w3, acc[r]);
        }
    }
    for (int i = 112; i < 115; i++) {
        float w0 = Wp[i * WID + c];
#pragma unroll
        for (int r = 0; r < BRP; r++) acc[r] = fmaf(fs[r * 120 + i], w0, acc[r]);
    }

#pragma unroll
    for (int r = 0; r < BRP; r++) {
        int row = row0 + r;
        if (row < n) g_hbf[0][(size_t)row * WID + c] = pack_hl(silu(acc[r]));
    }
}

// ---------------- weight prep: bf16 hi/lo, mma-fragment-linear order --------
// layout: [li][kc(12)][nt(48)][split(2)][t(32)][reg(2)] u32
__global__ void wprep_kernel(const float* __restrict__ Wl_all) {
    int gid = blockIdx.x * blockDim.x + threadIdx.x;
    if (gid >= NL * LI_WORDS) return;
    int li = gid / LI_WORDS;
    int r  = gid % LI_WORDS;
    int kc = r / SLAB;          r %= SLAB;
    int nt = r / 128;           r %= 128;
    int split = r / 64;         r %= 64;
    int t  = r / 2;
    int reg = r % 2;

    int k0 = kc * 16 + (t % 4) * 2 + reg * 8;
    int ncol = nt * 8 + t / 4;
    const float* W = Wl_all + (size_t)li * MIXD * WID;

    float v0, v1;
    if (ncol < 192) {
        v0 = W[(size_t)k0 * WID + ncol];
        v1 = W[(size_t)(k0 + 1) * WID + ncol];
    } else {
        v0 = W[(size_t)(192 + k0) * WID + (ncol - 192)];
        v1 = W[(size_t)(192 + k0 + 1) * WID + (ncol - 192)];
    }
    unsigned short b0, b1;
    if (split == 0) {
        b0 = __bfloat16_as_ushort(__float2bfloat16(v0));
        b1 = __bfloat16_as_ushort(__float2bfloat16(v1));
    } else {
        float h0 = __bfloat162float(__float2bfloat16(v0));
        float h1 = __bfloat162float(__float2bfloat16(v1));
        b0 = __bfloat16_as_ushort(__float2bfloat16(v0 - h0));
        b1 = __bfloat16_as_ushort(__float2bfloat16(v1 - h1));
    }
    g_Bfrag[gid] = (uint32_t)b0 | ((uint32_t)b1 << 16);
}

// ---------------- layer GEMM: [P|Y] = h . [W1|W2] via mma.sync bf16x3 -------
__global__ void __launch_bounds__(512, 1) layer_gemm_kernel(int src, int li, int n) {
    extern __shared__ uint32_t smw[];
    uint32_t* sA = smw;                  // 64 x 196 (padded)
    uint32_t* sB = smw + SA_WORDS;       // 2 x SLAB

    const int tid = threadIdx.x;
    const int lane = tid & 31;
    const int w = tid >> 5;
    const int mgroup = w & 1;            // 0/1 -> 32-row half
    const int ngroup = w >> 1;           // 0..7 -> 48-col group
    const int row0 = blockIdx.x * GEMM_M;
    const uint32_t* __restrict__ hin = g_hbf[src];
    const uint32_t* __restrict__ gB = g_Bfrag + (size_t)li * LI_WORDS;
    const uint32_t sb_base = (uint32_t)__cvta_generic_to_shared(sB);

    // stage A (64 rows x 192 u32) into padded smem
    for (int i = tid; i < 64 * 48; i += 512) {
        int r = i / 48, qd = i % 48;
        uint4 v = make_uint4(0u, 0u, 0u, 0u);
        int row = row0 + r;
        if (row < n) v = *(const uint4*)(hin + (size_t)row * WID + qd * 4);
        *(uint4*)(sA + r * SA_STRIDE + qd * 4) = v;
    }

    // cp.async B slab loaders (2-deep pipeline)
#define ISSUE_B(KC)                                                          \
    do {                                                                     \
        int _st = (KC) & 1;                                                  \
        const uint4* _src = (const uint4*)gB + (KC) * (SLAB / 4);            \
        _Pragma("unroll")                                                    \
        for (int _s = 0; _s < 3; _s++) {                                     \
            int _idx = tid + _s * 512;                                       \
            uint32_t _d = sb_base + (uint32_t)(_st * SLAB + _idx * 4) * 4u;  \
            asm volatile("cp.async.cg.shared.global [%0], [%1], 16;"         \
                         :: "r"(_d), "l"(_src + _idx));                      \
        }                                                                    \
        asm volatile("cp.async.commit_group;" ::: "memory");                 \
    } while (0)

    ISSUE_B(0);
    ISSUE_B(1);

    float c[2][6][4];
#pragma unroll
    for (int mt = 0; mt < 2; mt++)
#pragma unroll
        for (int nt = 0; nt < 6; nt++)
#pragma unroll
            for (int q = 0; q < 4; q++) c[mt][nt][q] = 0.f;

    for (int kc = 0; kc < 12; kc++) {
        if (kc < 10) asm volatile("cp.async.wait_group 1;" ::: "memory");
        else         asm volatile("cp.async.wait_group 0;" ::: "memory");
        __syncthreads();

        // A fragments (hi & lo) for both 16-row tiles
        uint32_t ah[2][4], al[2][4];
#pragma unroll
        for (int mt = 0; mt < 2; mt++) {
            int r = mgroup * 32 + mt * 16 + lane / 4;
            int kb = kc * 16 + (lane % 4) * 2;
            uint2 p0 = *(const uint2*)(sA + r * SA_STRIDE + kb);
            uint2 p1 = *(const uint2*)(sA + (r + 8) * SA_STRIDE + kb);
            uint2 p2 = *(const uint2*)(sA + r * SA_STRIDE + kb + 8);
            uint2 p3 = *(const uint2*)(sA + (r + 8) * SA_STRIDE + kb + 8);
            ah[mt][0] = __byte_perm(p0.x, p0.y, 0x7632); al[mt][0] = __byte_perm(p0.x, p0.y, 0x5410);
            ah[mt][1] = __byte_perm(p1.x, p1.y, 0x7632); al[mt][1] = __byte_perm(p1.x, p1.y, 0x5410);
            ah[mt][2] = __byte_perm(p2.x, p2.y, 0x7632); al[mt][2] = __byte_perm(p2.x, p2.y, 0x5410);
            ah[mt][3] = __byte_perm(p3.x, p3.y, 0x7632); al[mt][3] = __byte_perm(p3.x, p3.y, 0x5410);
        }

        const uint32_t* sBk = sB + (kc & 1) * SLAB;
#pragma unroll
        for (int nt = 0; nt < 6; nt++) {
            int ntg = ngroup * 6 + nt;
            uint2 bh = *(const uint2*)(sBk + (ntg * 2 + 0) * 64 + lane * 2);
            uint2 bl = *(const uint2*)(sBk + (ntg * 2 + 1) * 64 + lane * 2);
#pragma unroll
            for (int mt = 0; mt < 2; mt++) {
                MMA4(c[mt][nt], ah[mt][0], ah[mt][1], ah[mt][2], ah[mt][3], bh.x, bh.y);
                MMA4(c[mt][nt], al[mt][0], al[mt][1], al[mt][2], al[mt][3], bh.x, bh.y);
                MMA4(c[mt][nt], ah[mt][0], ah[mt][1], ah[mt][2], ah[mt][3], bl.x, bl.y);
            }
        }
        __syncthreads();
        if (kc + 2 < 12) ISSUE_B(kc + 2);
    }
#undef ISSUE_B

    // epilogue: write P (cols < 192) / Y (cols >= 192) as f32
#pragma unroll
    for (int mt = 0; mt < 2; mt++) {
        int R0 = row0 + mgroup * 32 + mt * 16 + lane / 4;
#pragma unroll
        for (int nt = 0; nt < 6; nt++) {
            int col = (ngroup * 6 + nt) * 8 + (lane % 4) * 2;
            float* dst = (col < 192) ? g_P : g_Yv;
            int cc = (col < 192) ? col : (col - 192);
            if (R0 < n)
                *(float2*)(dst + (size_t)R0 * WID + cc) = make_float2(c[mt][nt][0], c[mt][nt][1]);
            if (R0 + 8 < n)
                *(float2*)(dst + (size_t)(R0 + 8) * WID + cc) = make_float2(c[mt][nt][2], c[mt][nt][3]);
        }
    }
}

// ---------------- gather + activation ----------------------------------------
// h' = FiLM(silu(P + mean_j Y[knn_j] + rel.W3 + b)), packed to bf16 hi/lo
__global__ void __launch_bounds__(192) gather_act_kernel(int dst, int li,
                             const float* __restrict__ Wl_all,
                             const float* __restrict__ bl_all,
                             int n) {
    const int c = threadIdx.x;  // 192
    const float* __restrict__ W3 = Wl_all + (size_t)li * MIXD * WID + 384 * WID;

    float w3[6];
#pragma unroll
    for (int i = 0; i < 6; i++) w3[i] = W3[i * WID + c];
    const float b  = bl_all[li * WID + c];
    const float ga = g_gamma[li * WID + c];
    const float be = g_beta[li * WID + c];
    const float inv = 1.f / (float)KNN;

    const int row0 = blockIdx.x * 16;
    for (int r = 0; r < 16; r++) {
        int row = row0 + r;
        if (row >= n) return;
        float acc = g_P[(size_t)row * WID + c] + b;
        const int4* nbp = (const int4*)&g_knn[row * KNN];
        int4 na = nbp[0], nb = nbp[1], nc = nbp[2];
        int ids[KNN] = {na.x, na.y, na.z, na.w, nb.x, nb.y, nb.z, nb.w,
                        nc.x, nc.y, nc.z, nc.w};
        float s = 0.f;
#pragma unroll
        for (int j = 0; j < KNN; j++)
            s += g_Yv[(size_t)ids[j] * WID + c];
        acc = fmaf(s, inv, acc);
        const float* rel = g_rel + row * 6;
#pragma unroll
        for (int i = 0; i < 6; i++) acc = fmaf(rel[i], w3[i], acc);
        g_hbf[dst][(size_t)row * WID + c] = pack_hl(fmaf(silu(acc), ga, be));
    }
}

// ---------------- output head: (h @ Wout + bout) * 0.01, scatter to orig ----
__global__ void out_kernel(const float* __restrict__ Wout,
                           const float* __restrict__ bout,
                           float* __restrict__ out, int n) {
    const uint32_t* __restrict__ hin = g_hbf[0];  // after 4 layers: 0->1->0->1->0
    int gtid = blockIdx.x * blockDim.x + threadIdx.x;
    int warp = gtid >> 5;
    int lane = threadIdx.x & 31;
    if (warp >= n) return;
    float a0 = 0.f, a1 = 0.f, a2 = 0.f;
    for (int i = lane; i < WID; i += 32) {
        float h = unpack_hl(hin[(size_t)warp * WID + i]);
        a0 = fmaf(h, Wout[i * 3 + 0], a0);
        a1 = fmaf(h, Wout[i * 3 + 1], a1);
        a2 = fmaf(h, Wout[i * 3 + 2], a2);
    }
#pragma unroll
    for (int o = 16; o; o >>= 1) {
        a0 += __shfl_down_sync(0xffffffffu, a0, o);
        a1 += __shfl_down_sync(0xffffffffu, a1, o);
        a2 += __shfl_down_sync(0xffffffffu, a2, o);
    }
    if (lane == 0) {
        int orig = g_sorted_orig[warp];
        out[orig * 3 + 0] = (a0 + bout[0]) * 0.01f;
        out[orig * 3 + 1] = (a1 + bout[1]) * 0.01f;
        out[orig * 3 + 2] = (a2 + bout[2]) * 0.01f;
    }
}

// ---------------- launch -----------------------------------------------------
extern "C" void kernel_launch(void* const* d_in, const int* in_sizes, int n_in,
                              void* d_out, int out_size) {
    const float* x    = (const float*)d_in[0];
    const float* z    = (const float*)d_in[1];
    const float* B0   = (const float*)d_in[2];
    const float* B1   = (const float*)d_in[3];
    const float* B2   = (const float*)d_in[4];
    const float* Wp   = (const float*)d_in[5];
    const float* bp   = (const float*)d_in[6];
    const float* Wl   = (const float*)d_in[7];
    const float* bl   = (const float*)d_in[8];
    const float* Wg   = (const float*)d_in[9];
    const float* bg   = (const float*)d_in[10];
    const float* Wb   = (const float*)d_in[11];
    const float* bb   = (const float*)d_in[12];
    const float* Wout = (const float*)d_in[13];
    const float* bout = (const float*)d_in[14];
    float* out = (float*)d_out;

    const int n = in_sizes[0] / 3;
    const int smem_bytes = SM_WORDS * 4;

    static int attr_set = 0;
    cudaFuncSetAttribute(layer_gemm_kernel,
                         cudaFuncAttributeMaxDynamicSharedMemorySize, smem_bytes);
    (void)attr_set;

    // spatial-grid kNN (32^3 cells), sorted index space
    grid_zero_kernel<<<(CELLS + 255) / 256, 256>>>();
    grid_hist_kernel<<<(n + 255) / 256, 256>>>(x, n);
    grid_scan_kernel<<<1, 1024>>>();
    grid_scatter_kernel<<<(n + 255) / 256, 256>>>(x, n);
    knn_search_kernel<<<(n + 127) / 128, 128>>>(n);

    film_kernel<<<NL, WID>>>(z, Wg, bg, Wb, bb);
    prep_kernel<<<(n + BRP - 1) / BRP, WID>>>(z, B0, B1, B2, Wp, bp, n);
    wprep_kernel<<<(NL * LI_WORDS + 255) / 256, 256>>>(Wl);

    int src = 0;
    for (int li = 0; li < NL; li++) {
        int dst = 1 - src;
        layer_gemm_kernel<<<(n + GEMM_M - 1) / GEMM_M, 512, smem_bytes>>>(src, li, n);
        gather_act_kernel<<<(n + 15) / 16, WID>>>(dst, li, Wl, bl, n);
        src = dst;
    }

    out_kernel<<<(n * 32 + 255) / 256, 256>>>(Wout, bout, out, n);
}